// round 2
// baseline (speedup 1.0000x reference)
#include <cuda_runtime.h>
#include <cstdint>

// ---------------- constants ----------------
#define CHAMFER_W 1.0
#define NORMAL_W 0.5
#define EDGE_W 0.3
#define WATERTIGHT_W 0.2
#define SDF_W 1.0
#define DIHEDRAL_THRESHOLD 0.5f
#define EPS_COS 1e-8f
#define EPS_NRM 1e-12f

#define HBITS 18
#define HSIZE (1 << HBITS)
#define HMASK (HSIZE - 1)
#define EMPTY_KEY 0xFFFFFFFFFFFFFFFFull

// ---------------- device scratch (static, no allocs) ----------------
__device__ unsigned long long g_hkey[HSIZE];
__device__ int g_hcount[HSIZE];
__device__ int g_hfA[HSIZE];
__device__ int g_hfB[HSIZE];

__device__ double g_sdf_sum;
__device__ double g_p2g_sum;
__device__ double g_g2p_sum;
__device__ double g_norm_sum;
__device__ double g_sharp_sum;
__device__ int g_runs;
__device__ int g_pairs;

// ---------------- clear ----------------
__global__ void k_clear() {
    int i = blockIdx.x * blockDim.x + threadIdx.x;
    if (i < HSIZE) {
        g_hkey[i] = EMPTY_KEY;
        g_hcount[i] = 0;
    }
    if (i == 0) {
        g_sdf_sum = 0.0; g_p2g_sum = 0.0; g_g2p_sum = 0.0;
        g_norm_sum = 0.0; g_sharp_sum = 0.0;
        g_runs = 0; g_pairs = 0;
    }
}

// ---------------- SDF L1 ----------------
__global__ void k_sdf(const float* __restrict__ a, const float* __restrict__ b, int n) {
    __shared__ float sm[256];
    float s = 0.f;
    for (int i = blockIdx.x * blockDim.x + threadIdx.x; i < n; i += gridDim.x * blockDim.x)
        s += fabsf(a[i] - b[i]);
    sm[threadIdx.x] = s;
    __syncthreads();
    for (int off = 128; off > 0; off >>= 1) {
        if (threadIdx.x < off) sm[threadIdx.x] += sm[threadIdx.x + off];
        __syncthreads();
    }
    if (threadIdx.x == 0) atomicAdd(&g_sdf_sum, (double)sm[0]);
}

// ---------------- chamfer p->g (min + argmin + normal term) ----------------
#define TG 1024
#define WPB 8   // warps per block (blockDim = 256)

__global__ void k_p2g(const float* __restrict__ pp, const float* __restrict__ gp,
                      const float* __restrict__ pn, const float* __restrict__ gn,
                      int N, int M) {
    __shared__ float4 tile[TG];
    __shared__ float s_min[WPB], s_nrm[WPB];

    const int warp = threadIdx.x >> 5;
    const int lane = threadIdx.x & 31;
    const int p = blockIdx.x * WPB + warp;

    float px = 0.f, py = 0.f, pz = 0.f, p2 = 0.f;
    if (p < N) {
        px = pp[3 * p]; py = pp[3 * p + 1]; pz = pp[3 * p + 2];
        p2 = px * px + py * py + pz * pz;
    }

    float best = 3.4e38f;
    int bi = 0;

    for (int t0 = 0; t0 < M; t0 += TG) {
        int cnt = min(TG, M - t0);
        for (int j = threadIdx.x; j < cnt; j += blockDim.x) {
            const float* g = gp + 3 * (t0 + j);
            float gx = g[0], gy = g[1], gz = g[2];
            tile[j] = make_float4(gx, gy, gz, gx * gx + gy * gy + gz * gz);
        }
        __syncthreads();
        #pragma unroll 4
        for (int j = lane; j < cnt; j += 32) {
            float4 g = tile[j];
            float d = p2 + g.w - 2.f * (px * g.x + py * g.y + pz * g.z);
            int gj = t0 + j;
            if (d < best) { best = d; bi = gj; }
        }
        __syncthreads();
    }

    // warp argmin reduce (first-index tie-break)
    for (int off = 16; off > 0; off >>= 1) {
        float ov = __shfl_down_sync(0xffffffffu, best, off);
        int oi = __shfl_down_sync(0xffffffffu, bi, off);
        if (ov < best || (ov == best && oi < bi)) { best = ov; bi = oi; }
    }

    if (lane == 0) {
        float mn = 0.f, term = 0.f;
        if (p < N) {
            mn = best;
            float ax = pn[3 * p], ay = pn[3 * p + 1], az = pn[3 * p + 2];
            float bx = gn[3 * bi], by = gn[3 * bi + 1], bz = gn[3 * bi + 2];
            float na = fmaxf(sqrtf(ax * ax + ay * ay + az * az), EPS_COS);
            float nb = fmaxf(sqrtf(bx * bx + by * by + bz * bz), EPS_COS);
            float c = (ax * bx + ay * by + az * bz) / (na * nb);
            term = 1.f - fabsf(c);
        }
        s_min[warp] = mn;
        s_nrm[warp] = term;
    }
    __syncthreads();
    if (threadIdx.x == 0) {
        float smm = 0.f, snn = 0.f;
        #pragma unroll
        for (int w = 0; w < WPB; w++) { smm += s_min[w]; snn += s_nrm[w]; }
        atomicAdd(&g_p2g_sum, (double)smm);
        atomicAdd(&g_norm_sum, (double)snn);
    }
}

// ---------------- chamfer g->p (min only) ----------------
__global__ void k_g2p(const float* __restrict__ gp, const float* __restrict__ pp,
                      int M, int N) {
    __shared__ float4 tile[TG];
    __shared__ float s_min[WPB];

    const int warp = threadIdx.x >> 5;
    const int lane = threadIdx.x & 31;
    const int q = blockIdx.x * WPB + warp;

    float qx = 0.f, qy = 0.f, qz = 0.f, q2 = 0.f;
    if (q < M) {
        qx = gp[3 * q]; qy = gp[3 * q + 1]; qz = gp[3 * q + 2];
        q2 = qx * qx + qy * qy + qz * qz;
    }

    float best = 3.4e38f;

    for (int t0 = 0; t0 < N; t0 += TG) {
        int cnt = min(TG, N - t0);
        for (int j = threadIdx.x; j < cnt; j += blockDim.x) {
            const float* g = pp + 3 * (t0 + j);
            float gx = g[0], gy = g[1], gz = g[2];
            tile[j] = make_float4(gx, gy, gz, gx * gx + gy * gy + gz * gz);
        }
        __syncthreads();
        #pragma unroll 4
        for (int j = lane; j < cnt; j += 32) {
            float4 g = tile[j];
            float d = q2 + g.w - 2.f * (qx * g.x + qy * g.y + qz * g.z);
            best = fminf(best, d);
        }
        __syncthreads();
    }

    for (int off = 16; off > 0; off >>= 1)
        best = fminf(best, __shfl_down_sync(0xffffffffu, best, off));

    if (lane == 0) s_min[warp] = (q < M) ? best : 0.f;
    __syncthreads();
    if (threadIdx.x == 0) {
        float smm = 0.f;
        #pragma unroll
        for (int w = 0; w < WPB; w++) smm += s_min[w];
        atomicAdd(&g_g2p_sum, (double)smm);
    }
}

// ---------------- edge hash insert ----------------
__global__ void k_edges(const int* __restrict__ faces, int F, int V) {
    int e = blockIdx.x * blockDim.x + threadIdx.x;
    if (e >= 3 * F) return;
    int f = e / 3, k = e - 3 * f;
    int a = faces[3 * f + k];
    int b = faces[3 * f + ((k + 1) % 3)];
    int lo = min(a, b), hi = max(a, b);
    unsigned long long key = (unsigned long long)(unsigned)lo * (unsigned)V + (unsigned)hi;

    unsigned h = (unsigned)((key * 0x9E3779B97F4A7C15ull) >> 40) & HMASK;
    while (true) {
        unsigned long long prev = atomicCAS(&g_hkey[h], EMPTY_KEY, key);
        if (prev == EMPTY_KEY || prev == key) break;
        h = (h + 1) & HMASK;
    }
    int c = atomicAdd(&g_hcount[h], 1);
    if (c == 0) g_hfA[h] = f;
    else if (c == 1) g_hfB[h] = f;
}

// ---------------- edge finalize ----------------
__device__ __forceinline__ float3 face_normal(const float* __restrict__ verts,
                                              const int* __restrict__ faces, int f) {
    int i0 = faces[3 * f], i1 = faces[3 * f + 1], i2 = faces[3 * f + 2];
    float v0x = verts[3 * i0], v0y = verts[3 * i0 + 1], v0z = verts[3 * i0 + 2];
    float v1x = verts[3 * i1], v1y = verts[3 * i1 + 1], v1z = verts[3 * i1 + 2];
    float v2x = verts[3 * i2], v2y = verts[3 * i2 + 1], v2z = verts[3 * i2 + 2];
    float e1x = v1x - v0x, e1y = v1y - v0y, e1z = v1z - v0z;
    float e2x = v2x - v0x, e2y = v2y - v0y, e2z = v2z - v0z;
    float nx = e1y * e2z - e1z * e2y;
    float ny = e1z * e2x - e1x * e2z;
    float nz = e1x * e2y - e1y * e2x;
    float nrm = fmaxf(sqrtf(nx * nx + ny * ny + nz * nz), EPS_NRM);
    return make_float3(nx / nrm, ny / nrm, nz / nrm);
}

__global__ void k_edge_final(const float* __restrict__ verts, const int* __restrict__ faces) {
    __shared__ int sm_runs[256];
    __shared__ int sm_pairs[256];
    __shared__ float sm_sharp[256];

    int i = blockIdx.x * blockDim.x + threadIdx.x;
    int runs = 0, pairs = 0;
    float sharp = 0.f;
    if (i < HSIZE && g_hkey[i] != EMPTY_KEY) {
        runs = 1;
        if (g_hcount[i] == 2) {
            pairs = 1;
            float3 na = face_normal(verts, faces, g_hfA[i]);
            float3 nb = face_normal(verts, faces, g_hfB[i]);
            float c = na.x * nb.x + na.y * nb.y + na.z * nb.z;
            sharp = fmaxf(c - DIHEDRAL_THRESHOLD, 0.f);
        }
    }
    sm_runs[threadIdx.x] = runs;
    sm_pairs[threadIdx.x] = pairs;
    sm_sharp[threadIdx.x] = sharp;
    __syncthreads();
    for (int off = 128; off > 0; off >>= 1) {
        if (threadIdx.x < off) {
            sm_runs[threadIdx.x] += sm_runs[threadIdx.x + off];
            sm_pairs[threadIdx.x] += sm_pairs[threadIdx.x + off];
            sm_sharp[threadIdx.x] += sm_sharp[threadIdx.x + off];
        }
        __syncthreads();
    }
    if (threadIdx.x == 0) {
        if (sm_runs[0]) atomicAdd(&g_runs, sm_runs[0]);
        if (sm_pairs[0]) atomicAdd(&g_pairs, sm_pairs[0]);
        if (sm_sharp[0] != 0.f) atomicAdd(&g_sharp_sum, (double)sm_sharp[0]);
    }
}

// ---------------- combine ----------------
__global__ void k_out(float* __restrict__ out, int NS, int N, int M) {
    double sdf = SDF_W * (g_sdf_sum / (double)NS);
    double ch = CHAMFER_W * (g_p2g_sum / (double)N + g_g2p_sum / (double)M);
    double nl = NORMAL_W * (g_norm_sum / (double)N);
    double el = EDGE_W * ((g_pairs > 0) ? (g_sharp_sum / (double)g_pairs) : 0.0);
    double wl = WATERTIGHT_W * ((g_runs > 0) ? ((double)(g_runs - g_pairs) / (double)g_runs) : 0.0);
    out[0] = (float)sdf;
    out[1] = (float)ch;
    out[2] = (float)nl;
    out[3] = (float)el;
    out[4] = (float)wl;
    out[5] = (float)(sdf + ch + nl + el + wl);
}

// ---------------- launch ----------------
extern "C" void kernel_launch(void* const* d_in, const int* in_sizes, int n_in,
                              void* d_out, int out_size) {
    const float* pred_sdf = (const float*)d_in[0];
    const float* gt_sdf   = (const float*)d_in[1];
    const float* ext_verts = (const float*)d_in[2];
    const int*   ext_faces = (const int*)d_in[3];
    // d_in[4], d_in[5]: gt mesh — unused by the reference loss
    const float* pred_pts = (const float*)d_in[6];
    const float* gt_pts   = (const float*)d_in[7];
    const float* pred_nrm = (const float*)d_in[8];
    const float* gt_nrm   = (const float*)d_in[9];

    const int NS = in_sizes[0];
    const int V  = in_sizes[2] / 3;
    const int F  = in_sizes[3] / 3;
    const int N  = in_sizes[6] / 3;
    const int M  = in_sizes[7] / 3;

    k_clear<<<(HSIZE + 255) / 256, 256>>>();
    k_sdf<<<256, 256>>>(pred_sdf, gt_sdf, NS);
    k_p2g<<<(N + WPB - 1) / WPB, 256>>>(pred_pts, gt_pts, pred_nrm, gt_nrm, N, M);
    k_g2p<<<(M + WPB - 1) / WPB, 256>>>(gt_pts, pred_pts, M, N);
    k_edges<<<(3 * F + 255) / 256, 256>>>(ext_faces, F, V);
    k_edge_final<<<(HSIZE + 255) / 256, 256>>>(ext_verts, ext_faces);
    k_out<<<1, 1>>>((float*)d_out, NS, N, M);
}

// round 5
// speedup vs baseline: 1.0015x; 1.0015x over previous
#include <cuda_runtime.h>
#include <cstdint>

// ---------------- constants ----------------
#define CHAMFER_W 1.0
#define NORMAL_W 0.5
#define EDGE_W 0.3
#define WATERTIGHT_W 0.2
#define SDF_W 1.0
#define DIHEDRAL_THRESHOLD 0.5f
#define EPS_COS 1e-8f
#define EPS_NRM 1e-12f

#define HBITS 18
#define HSIZE (1 << HBITS)
#define HMASK (HSIZE - 1)
#define EMPTY_KEY 0xFFFFFFFFFFFFFFFFull

// ---------------- device scratch (static, no allocs) ----------------
__device__ unsigned long long g_hkey[HSIZE];
__device__ int g_hcount[HSIZE];
__device__ int g_hfA[HSIZE];
__device__ int g_hfB[HSIZE];

__device__ double g_sdf_sum;
__device__ double g_p2g_sum;
__device__ double g_g2p_sum;
__device__ double g_norm_sum;
__device__ double g_sharp_sum;
__device__ int g_runs;
__device__ int g_pairs;

// ---------------- clear ----------------
__global__ void k_clear() {
    int i = blockIdx.x * blockDim.x + threadIdx.x;
    if (i < HSIZE) {
        g_hkey[i] = EMPTY_KEY;
        g_hcount[i] = 0;
    }
    if (i == 0) {
        g_sdf_sum = 0.0; g_p2g_sum = 0.0; g_g2p_sum = 0.0;
        g_norm_sum = 0.0; g_sharp_sum = 0.0;
        g_runs = 0; g_pairs = 0;
    }
}

// ---------------- SDF L1 ----------------
__global__ void k_sdf(const float* __restrict__ a, const float* __restrict__ b, int n) {
    __shared__ float sm[256];
    float s = 0.f;
    for (int i = blockIdx.x * blockDim.x + threadIdx.x; i < n; i += gridDim.x * blockDim.x)
        s += fabsf(a[i] - b[i]);
    sm[threadIdx.x] = s;
    __syncthreads();
    for (int off = 128; off > 0; off >>= 1) {
        if (threadIdx.x < off) sm[threadIdx.x] += sm[threadIdx.x + off];
        __syncthreads();
    }
    if (threadIdx.x == 0) atomicAdd(&g_sdf_sum, (double)sm[0]);
}

// ---------------- chamfer p->g (min + argmin + normal term) ----------------
#define TG 1024
#define WPB 8   // warps per block (blockDim = 256)

__global__ void k_p2g(const float* __restrict__ pp, const float* __restrict__ gp,
                      const float* __restrict__ pn, const float* __restrict__ gn,
                      int N, int M) {
    __shared__ float4 tile[TG];
    __shared__ float s_min[WPB], s_nrm[WPB];

    const int warp = threadIdx.x >> 5;
    const int lane = threadIdx.x & 31;
    const int p = blockIdx.x * WPB + warp;

    float px = 0.f, py = 0.f, pz = 0.f, p2 = 0.f;
    if (p < N) {
        px = pp[3 * p]; py = pp[3 * p + 1]; pz = pp[3 * p + 2];
        p2 = px * px + py * py + pz * pz;
    }

    float best = 3.4e38f;
    int bi = 0;

    for (int t0 = 0; t0 < M; t0 += TG) {
        int cnt = min(TG, M - t0);
        for (int j = threadIdx.x; j < cnt; j += blockDim.x) {
            const float* g = gp + 3 * (t0 + j);
            float gx = g[0], gy = g[1], gz = g[2];
            tile[j] = make_float4(gx, gy, gz, gx * gx + gy * gy + gz * gz);
        }
        __syncthreads();
        #pragma unroll 4
        for (int j = lane; j < cnt; j += 32) {
            float4 g = tile[j];
            float d = p2 + g.w - 2.f * (px * g.x + py * g.y + pz * g.z);
            int gj = t0 + j;
            if (d < best) { best = d; bi = gj; }
        }
        __syncthreads();
    }

    // warp argmin reduce (first-index tie-break)
    for (int off = 16; off > 0; off >>= 1) {
        float ov = __shfl_down_sync(0xffffffffu, best, off);
        int oi = __shfl_down_sync(0xffffffffu, bi, off);
        if (ov < best || (ov == best && oi < bi)) { best = ov; bi = oi; }
    }

    if (lane == 0) {
        float mn = 0.f, term = 0.f;
        if (p < N) {
            mn = best;
            float ax = pn[3 * p], ay = pn[3 * p + 1], az = pn[3 * p + 2];
            float bx = gn[3 * bi], by = gn[3 * bi + 1], bz = gn[3 * bi + 2];
            float na = fmaxf(sqrtf(ax * ax + ay * ay + az * az), EPS_COS);
            float nb = fmaxf(sqrtf(bx * bx + by * by + bz * bz), EPS_COS);
            float c = (ax * bx + ay * by + az * bz) / (na * nb);
            term = 1.f - fabsf(c);
        }
        s_min[warp] = mn;
        s_nrm[warp] = term;
    }
    __syncthreads();
    if (threadIdx.x == 0) {
        float smm = 0.f, snn = 0.f;
        #pragma unroll
        for (int w = 0; w < WPB; w++) { smm += s_min[w]; snn += s_nrm[w]; }
        atomicAdd(&g_p2g_sum, (double)smm);
        atomicAdd(&g_norm_sum, (double)snn);
    }
}

// ---------------- chamfer g->p (min only) ----------------
__global__ void k_g2p(const float* __restrict__ gp, const float* __restrict__ pp,
                      int M, int N) {
    __shared__ float4 tile[TG];
    __shared__ float s_min[WPB];

    const int warp = threadIdx.x >> 5;
    const int lane = threadIdx.x & 31;
    const int q = blockIdx.x * WPB + warp;

    float qx = 0.f, qy = 0.f, qz = 0.f, q2 = 0.f;
    if (q < M) {
        qx = gp[3 * q]; qy = gp[3 * q + 1]; qz = gp[3 * q + 2];
        q2 = qx * qx + qy * qy + qz * qz;
    }

    float best = 3.4e38f;

    for (int t0 = 0; t0 < N; t0 += TG) {
        int cnt = min(TG, N - t0);
        for (int j = threadIdx.x; j < cnt; j += blockDim.x) {
            const float* g = pp + 3 * (t0 + j);
            float gx = g[0], gy = g[1], gz = g[2];
            tile[j] = make_float4(gx, gy, gz, gx * gx + gy * gy + gz * gz);
        }
        __syncthreads();
        #pragma unroll 4
        for (int j = lane; j < cnt; j += 32) {
            float4 g = tile[j];
            float d = q2 + g.w - 2.f * (qx * g.x + qy * g.y + qz * g.z);
            best = fminf(best, d);
        }
        __syncthreads();
    }

    for (int off = 16; off > 0; off >>= 1)
        best = fminf(best, __shfl_down_sync(0xffffffffu, best, off));

    if (lane == 0) s_min[warp] = (q < M) ? best : 0.f;
    __syncthreads();
    if (threadIdx.x == 0) {
        float smm = 0.f;
        #pragma unroll
        for (int w = 0; w < WPB; w++) smm += s_min[w];
        atomicAdd(&g_g2p_sum, (double)smm);
    }
}

// ---------------- edge hash insert ----------------
__global__ void k_edges(const int* __restrict__ faces, int F, int V) {
    int e = blockIdx.x * blockDim.x + threadIdx.x;
    if (e >= 3 * F) return;
    int f = e / 3, k = e - 3 * f;
    int a = faces[3 * f + k];
    int b = faces[3 * f + ((k + 1) % 3)];
    int lo = min(a, b), hi = max(a, b);
    unsigned long long key = (unsigned long long)(unsigned)lo * (unsigned)V + (unsigned)hi;

    unsigned h = (unsigned)((key * 0x9E3779B97F4A7C15ull) >> 40) & HMASK;
    while (true) {
        unsigned long long prev = atomicCAS(&g_hkey[h], EMPTY_KEY, key);
        if (prev == EMPTY_KEY || prev == key) break;
        h = (h + 1) & HMASK;
    }
    int c = atomicAdd(&g_hcount[h], 1);
    if (c == 0) g_hfA[h] = f;
    else if (c == 1) g_hfB[h] = f;
}

// ---------------- edge finalize ----------------
__device__ __forceinline__ float3 face_normal(const float* __restrict__ verts,
                                              const int* __restrict__ faces, int f) {
    int i0 = faces[3 * f], i1 = faces[3 * f + 1], i2 = faces[3 * f + 2];
    float v0x = verts[3 * i0], v0y = verts[3 * i0 + 1], v0z = verts[3 * i0 + 2];
    float v1x = verts[3 * i1], v1y = verts[3 * i1 + 1], v1z = verts[3 * i1 + 2];
    float v2x = verts[3 * i2], v2y = verts[3 * i2 + 1], v2z = verts[3 * i2 + 2];
    float e1x = v1x - v0x, e1y = v1y - v0y, e1z = v1z - v0z;
    float e2x = v2x - v0x, e2y = v2y - v0y, e2z = v2z - v0z;
    float nx = e1y * e2z - e1z * e2y;
    float ny = e1z * e2x - e1x * e2z;
    float nz = e1x * e2y - e1y * e2x;
    float nrm = fmaxf(sqrtf(nx * nx + ny * ny + nz * nz), EPS_NRM);
    return make_float3(nx / nrm, ny / nrm, nz / nrm);
}

__global__ void k_edge_final(const float* __restrict__ verts, const int* __restrict__ faces) {
    __shared__ int sm_runs[256];
    __shared__ int sm_pairs[256];
    __shared__ float sm_sharp[256];

    int i = blockIdx.x * blockDim.x + threadIdx.x;
    int runs = 0, pairs = 0;
    float sharp = 0.f;
    if (i < HSIZE && g_hkey[i] != EMPTY_KEY) {
        runs = 1;
        if (g_hcount[i] == 2) {
            pairs = 1;
            float3 na = face_normal(verts, faces, g_hfA[i]);
            float3 nb = face_normal(verts, faces, g_hfB[i]);
            float c = na.x * nb.x + na.y * nb.y + na.z * nb.z;
            sharp = fmaxf(c - DIHEDRAL_THRESHOLD, 0.f);
        }
    }
    sm_runs[threadIdx.x] = runs;
    sm_pairs[threadIdx.x] = pairs;
    sm_sharp[threadIdx.x] = sharp;
    __syncthreads();
    for (int off = 128; off > 0; off >>= 1) {
        if (threadIdx.x < off) {
            sm_runs[threadIdx.x] += sm_runs[threadIdx.x + off];
            sm_pairs[threadIdx.x] += sm_pairs[threadIdx.x + off];
            sm_sharp[threadIdx.x] += sm_sharp[threadIdx.x + off];
        }
        __syncthreads();
    }
    if (threadIdx.x == 0) {
        if (sm_runs[0]) atomicAdd(&g_runs, sm_runs[0]);
        if (sm_pairs[0]) atomicAdd(&g_pairs, sm_pairs[0]);
        if (sm_sharp[0] != 0.f) atomicAdd(&g_sharp_sum, (double)sm_sharp[0]);
    }
}

// ---------------- combine ----------------
__global__ void k_out(float* __restrict__ out, int NS, int N, int M) {
    double sdf = SDF_W * (g_sdf_sum / (double)NS);
    double ch = CHAMFER_W * (g_p2g_sum / (double)N + g_g2p_sum / (double)M);
    double nl = NORMAL_W * (g_norm_sum / (double)N);
    double el = EDGE_W * ((g_pairs > 0) ? (g_sharp_sum / (double)g_pairs) : 0.0);
    double wl = WATERTIGHT_W * ((g_runs > 0) ? ((double)(g_runs - g_pairs) / (double)g_runs) : 0.0);
    out[0] = (float)sdf;
    out[1] = (float)ch;
    out[2] = (float)nl;
    out[3] = (float)el;
    out[4] = (float)wl;
    out[5] = (float)(sdf + ch + nl + el + wl);
}

// ---------------- launch ----------------
extern "C" void kernel_launch(void* const* d_in, const int* in_sizes, int n_in,
                              void* d_out, int out_size) {
    const float* pred_sdf = (const float*)d_in[0];
    const float* gt_sdf   = (const float*)d_in[1];
    const float* ext_verts = (const float*)d_in[2];
    const int*   ext_faces = (const int*)d_in[3];
    // d_in[4], d_in[5]: gt mesh — unused by the reference loss
    const float* pred_pts = (const float*)d_in[6];
    const float* gt_pts   = (const float*)d_in[7];
    const float* pred_nrm = (const float*)d_in[8];
    const float* gt_nrm   = (const float*)d_in[9];

    const int NS = in_sizes[0];
    const int V  = in_sizes[2] / 3;
    const int F  = in_sizes[3] / 3;
    const int N  = in_sizes[6] / 3;
    const int M  = in_sizes[7] / 3;

    k_clear<<<(HSIZE + 255) / 256, 256>>>();
    k_sdf<<<256, 256>>>(pred_sdf, gt_sdf, NS);
    k_p2g<<<(N + WPB - 1) / WPB, 256>>>(pred_pts, gt_pts, pred_nrm, gt_nrm, N, M);
    k_g2p<<<(M + WPB - 1) / WPB, 256>>>(gt_pts, pred_pts, M, N);
    k_edges<<<(3 * F + 255) / 256, 256>>>(ext_faces, F, V);
    k_edge_final<<<(HSIZE + 255) / 256, 256>>>(ext_verts, ext_faces);
    k_out<<<1, 1>>>((float*)d_out, NS, N, M);
}

// round 8
// speedup vs baseline: 1.0047x; 1.0032x over previous
#include <cuda_runtime.h>
#include <cstdint>

// ---------------- constants ----------------
#define CHAMFER_W 1.0
#define NORMAL_W 0.5
#define EDGE_W 0.3
#define WATERTIGHT_W 0.2
#define SDF_W 1.0
#define DIHEDRAL_THRESHOLD 0.5f
#define EPS_COS 1e-8f
#define EPS_NRM 1e-12f

#define HBITS 18
#define HSIZE (1 << HBITS)
#define HMASK (HSIZE - 1)
#define EMPTY_KEY 0xFFFFFFFFFFFFFFFFull

// ---------------- device scratch (static, no allocs) ----------------
__device__ unsigned long long g_hkey[HSIZE];
__device__ int g_hcount[HSIZE];
__device__ int g_hfA[HSIZE];
__device__ int g_hfB[HSIZE];

__device__ double g_sdf_sum;
__device__ double g_p2g_sum;
__device__ double g_g2p_sum;
__device__ double g_norm_sum;
__device__ double g_sharp_sum;
__device__ int g_runs;
__device__ int g_pairs;

// ---------------- clear ----------------
__global__ void k_clear() {
    int i = blockIdx.x * blockDim.x + threadIdx.x;
    if (i < HSIZE) {
        g_hkey[i] = EMPTY_KEY;
        g_hcount[i] = 0;
    }
    if (i == 0) {
        g_sdf_sum = 0.0; g_p2g_sum = 0.0; g_g2p_sum = 0.0;
        g_norm_sum = 0.0; g_sharp_sum = 0.0;
        g_runs = 0; g_pairs = 0;
    }
}

// ---------------- SDF L1 ----------------
__global__ void k_sdf(const float* __restrict__ a, const float* __restrict__ b, int n) {
    __shared__ float sm[256];
    float s = 0.f;
    for (int i = blockIdx.x * blockDim.x + threadIdx.x; i < n; i += gridDim.x * blockDim.x)
        s += fabsf(a[i] - b[i]);
    sm[threadIdx.x] = s;
    __syncthreads();
    for (int off = 128; off > 0; off >>= 1) {
        if (threadIdx.x < off) sm[threadIdx.x] += sm[threadIdx.x + off];
        __syncthreads();
    }
    if (threadIdx.x == 0) atomicAdd(&g_sdf_sum, (double)sm[0]);
}

// ---------------- chamfer p->g (min + argmin + normal term) ----------------
#define TG 1024
#define WPB 8   // warps per block (blockDim = 256)

__global__ void k_p2g(const float* __restrict__ pp, const float* __restrict__ gp,
                      const float* __restrict__ pn, const float* __restrict__ gn,
                      int N, int M) {
    __shared__ float4 tile[TG];
    __shared__ float s_min[WPB], s_nrm[WPB];

    const int warp = threadIdx.x >> 5;
    const int lane = threadIdx.x & 31;
    const int p = blockIdx.x * WPB + warp;

    float px = 0.f, py = 0.f, pz = 0.f, p2 = 0.f;
    if (p < N) {
        px = pp[3 * p]; py = pp[3 * p + 1]; pz = pp[3 * p + 2];
        p2 = px * px + py * py + pz * pz;
    }

    float best = 3.4e38f;
    int bi = 0;

    for (int t0 = 0; t0 < M; t0 += TG) {
        int cnt = min(TG, M - t0);
        for (int j = threadIdx.x; j < cnt; j += blockDim.x) {
            const float* g = gp + 3 * (t0 + j);
            float gx = g[0], gy = g[1], gz = g[2];
            tile[j] = make_float4(gx, gy, gz, gx * gx + gy * gy + gz * gz);
        }
        __syncthreads();
        #pragma unroll 4
        for (int j = lane; j < cnt; j += 32) {
            float4 g = tile[j];
            float d = p2 + g.w - 2.f * (px * g.x + py * g.y + pz * g.z);
            int gj = t0 + j;
            if (d < best) { best = d; bi = gj; }
        }
        __syncthreads();
    }

    // warp argmin reduce (first-index tie-break)
    for (int off = 16; off > 0; off >>= 1) {
        float ov = __shfl_down_sync(0xffffffffu, best, off);
        int oi = __shfl_down_sync(0xffffffffu, bi, off);
        if (ov < best || (ov == best && oi < bi)) { best = ov; bi = oi; }
    }

    if (lane == 0) {
        float mn = 0.f, term = 0.f;
        if (p < N) {
            mn = best;
            float ax = pn[3 * p], ay = pn[3 * p + 1], az = pn[3 * p + 2];
            float bx = gn[3 * bi], by = gn[3 * bi + 1], bz = gn[3 * bi + 2];
            float na = fmaxf(sqrtf(ax * ax + ay * ay + az * az), EPS_COS);
            float nb = fmaxf(sqrtf(bx * bx + by * by + bz * bz), EPS_COS);
            float c = (ax * bx + ay * by + az * bz) / (na * nb);
            term = 1.f - fabsf(c);
        }
        s_min[warp] = mn;
        s_nrm[warp] = term;
    }
    __syncthreads();
    if (threadIdx.x == 0) {
        float smm = 0.f, snn = 0.f;
        #pragma unroll
        for (int w = 0; w < WPB; w++) { smm += s_min[w]; snn += s_nrm[w]; }
        atomicAdd(&g_p2g_sum, (double)smm);
        atomicAdd(&g_norm_sum, (double)snn);
    }
}

// ---------------- chamfer g->p (min only) ----------------
__global__ void k_g2p(const float* __restrict__ gp, const float* __restrict__ pp,
                      int M, int N) {
    __shared__ float4 tile[TG];
    __shared__ float s_min[WPB];

    const int warp = threadIdx.x >> 5;
    const int lane = threadIdx.x & 31;
    const int q = blockIdx.x * WPB + warp;

    float qx = 0.f, qy = 0.f, qz = 0.f, q2 = 0.f;
    if (q < M) {
        qx = gp[3 * q]; qy = gp[3 * q + 1]; qz = gp[3 * q + 2];
        q2 = qx * qx + qy * qy + qz * qz;
    }

    float best = 3.4e38f;

    for (int t0 = 0; t0 < N; t0 += TG) {
        int cnt = min(TG, N - t0);
        for (int j = threadIdx.x; j < cnt; j += blockDim.x) {
            const float* g = pp + 3 * (t0 + j);
            float gx = g[0], gy = g[1], gz = g[2];
            tile[j] = make_float4(gx, gy, gz, gx * gx + gy * gy + gz * gz);
        }
        __syncthreads();
        #pragma unroll 4
        for (int j = lane; j < cnt; j += 32) {
            float4 g = tile[j];
            float d = q2 + g.w - 2.f * (qx * g.x + qy * g.y + qz * g.z);
            best = fminf(best, d);
        }
        __syncthreads();
    }

    for (int off = 16; off > 0; off >>= 1)
        best = fminf(best, __shfl_down_sync(0xffffffffu, best, off));

    if (lane == 0) s_min[warp] = (q < M) ? best : 0.f;
    __syncthreads();
    if (threadIdx.x == 0) {
        float smm = 0.f;
        #pragma unroll
        for (int w = 0; w < WPB; w++) smm += s_min[w];
        atomicAdd(&g_g2p_sum, (double)smm);
    }
}

// ---------------- edge hash insert ----------------
__global__ void k_edges(const int* __restrict__ faces, int F, int V) {
    int e = blockIdx.x * blockDim.x + threadIdx.x;
    if (e >= 3 * F) return;
    int f = e / 3, k = e - 3 * f;
    int a = faces[3 * f + k];
    int b = faces[3 * f + ((k + 1) % 3)];
    int lo = min(a, b), hi = max(a, b);
    unsigned long long key = (unsigned long long)(unsigned)lo * (unsigned)V + (unsigned)hi;

    unsigned h = (unsigned)((key * 0x9E3779B97F4A7C15ull) >> 40) & HMASK;
    while (true) {
        unsigned long long prev = atomicCAS(&g_hkey[h], EMPTY_KEY, key);
        if (prev == EMPTY_KEY || prev == key) break;
        h = (h + 1) & HMASK;
    }
    int c = atomicAdd(&g_hcount[h], 1);
    if (c == 0) g_hfA[h] = f;
    else if (c == 1) g_hfB[h] = f;
}

// ---------------- edge finalize ----------------
__device__ __forceinline__ float3 face_normal(const float* __restrict__ verts,
                                              const int* __restrict__ faces, int f) {
    int i0 = faces[3 * f], i1 = faces[3 * f + 1], i2 = faces[3 * f + 2];
    float v0x = verts[3 * i0], v0y = verts[3 * i0 + 1], v0z = verts[3 * i0 + 2];
    float v1x = verts[3 * i1], v1y = verts[3 * i1 + 1], v1z = verts[3 * i1 + 2];
    float v2x = verts[3 * i2], v2y = verts[3 * i2 + 1], v2z = verts[3 * i2 + 2];
    float e1x = v1x - v0x, e1y = v1y - v0y, e1z = v1z - v0z;
    float e2x = v2x - v0x, e2y = v2y - v0y, e2z = v2z - v0z;
    float nx = e1y * e2z - e1z * e2y;
    float ny = e1z * e2x - e1x * e2z;
    float nz = e1x * e2y - e1y * e2x;
    float nrm = fmaxf(sqrtf(nx * nx + ny * ny + nz * nz), EPS_NRM);
    return make_float3(nx / nrm, ny / nrm, nz / nrm);
}

__global__ void k_edge_final(const float* __restrict__ verts, const int* __restrict__ faces) {
    __shared__ int sm_runs[256];
    __shared__ int sm_pairs[256];
    __shared__ float sm_sharp[256];

    int i = blockIdx.x * blockDim.x + threadIdx.x;
    int runs = 0, pairs = 0;
    float sharp = 0.f;
    if (i < HSIZE && g_hkey[i] != EMPTY_KEY) {
        runs = 1;
        if (g_hcount[i] == 2) {
            pairs = 1;
            float3 na = face_normal(verts, faces, g_hfA[i]);
            float3 nb = face_normal(verts, faces, g_hfB[i]);
            float c = na.x * nb.x + na.y * nb.y + na.z * nb.z;
            sharp = fmaxf(c - DIHEDRAL_THRESHOLD, 0.f);
        }
    }
    sm_runs[threadIdx.x] = runs;
    sm_pairs[threadIdx.x] = pairs;
    sm_sharp[threadIdx.x] = sharp;
    __syncthreads();
    for (int off = 128; off > 0; off >>= 1) {
        if (threadIdx.x < off) {
            sm_runs[threadIdx.x] += sm_runs[threadIdx.x + off];
            sm_pairs[threadIdx.x] += sm_pairs[threadIdx.x + off];
            sm_sharp[threadIdx.x] += sm_sharp[threadIdx.x + off];
        }
        __syncthreads();
    }
    if (threadIdx.x == 0) {
        if (sm_runs[0]) atomicAdd(&g_runs, sm_runs[0]);
        if (sm_pairs[0]) atomicAdd(&g_pairs, sm_pairs[0]);
        if (sm_sharp[0] != 0.f) atomicAdd(&g_sharp_sum, (double)sm_sharp[0]);
    }
}

// ---------------- combine ----------------
__global__ void k_out(float* __restrict__ out, int NS, int N, int M) {
    double sdf = SDF_W * (g_sdf_sum / (double)NS);
    double ch = CHAMFER_W * (g_p2g_sum / (double)N + g_g2p_sum / (double)M);
    double nl = NORMAL_W * (g_norm_sum / (double)N);
    double el = EDGE_W * ((g_pairs > 0) ? (g_sharp_sum / (double)g_pairs) : 0.0);
    double wl = WATERTIGHT_W * ((g_runs > 0) ? ((double)(g_runs - g_pairs) / (double)g_runs) : 0.0);
    out[0] = (float)sdf;
    out[1] = (float)ch;
    out[2] = (float)nl;
    out[3] = (float)el;
    out[4] = (float)wl;
    out[5] = (float)(sdf + ch + nl + el + wl);
}

// ---------------- launch ----------------
extern "C" void kernel_launch(void* const* d_in, const int* in_sizes, int n_in,
                              void* d_out, int out_size) {
    const float* pred_sdf = (const float*)d_in[0];
    const float* gt_sdf   = (const float*)d_in[1];
    const float* ext_verts = (const float*)d_in[2];
    const int*   ext_faces = (const int*)d_in[3];
    // d_in[4], d_in[5]: gt mesh — unused by the reference loss
    const float* pred_pts = (const float*)d_in[6];
    const float* gt_pts   = (const float*)d_in[7];
    const float* pred_nrm = (const float*)d_in[8];
    const float* gt_nrm   = (const float*)d_in[9];

    const int NS = in_sizes[0];
    const int V  = in_sizes[2] / 3;
    const int F  = in_sizes[3] / 3;
    const int N  = in_sizes[6] / 3;
    const int M  = in_sizes[7] / 3;

    k_clear<<<(HSIZE + 255) / 256, 256>>>();
    k_sdf<<<256, 256>>>(pred_sdf, gt_sdf, NS);
    k_p2g<<<(N + WPB - 1) / WPB, 256>>>(pred_pts, gt_pts, pred_nrm, gt_nrm, N, M);
    k_g2p<<<(M + WPB - 1) / WPB, 256>>>(gt_pts, pred_pts, M, N);
    k_edges<<<(3 * F + 255) / 256, 256>>>(ext_faces, F, V);
    k_edge_final<<<(HSIZE + 255) / 256, 256>>>(ext_verts, ext_faces);
    k_out<<<1, 1>>>((float*)d_out, NS, N, M);
}